// round 8
// baseline (speedup 1.0000x reference)
#include <cuda_runtime.h>
#include <math.h>

#define Nn 75000
#define Ee 150000
#define Hh 44
#define EDd 10
#define RSTR 12           // padded r row stride
#define NFf 15000
#define NGg 1500
#define HH2 1936
#define KSTR 492          // (legacy, unused by conv)
#define CSTRH 264         // per-half column count / stride
#define TILE 32
#define CAP 64            // max edges recorded per src node
#define LCAP 320          // per-tile packed edge capacity
#define NTILES ((Nn + TILE - 1) / TILE)
#define THC 384           // conv block threads

typedef unsigned long long ull;

// ---------------- scratch ----------------------------------------------------
__device__ float g_outA[Nn*Hh];
__device__ float g_outB[Nn*Hh];
__device__ float g_r[Ee*RSTR];
__device__ float g_Kbig2[2*Hh*CSTRH];
__device__ float g_agg[Nn*Hh];
__device__ int   g_deg[Nn];
__device__ int   g_noff[Nn];
__device__ int   g_tab[Nn*CAP];
__device__ int   g_tdst[NTILES*LCAP];
__device__ int   g_tln[NTILES*LCAP];
__device__ int   g_tcnt[NTILES];
__device__ float g_tr[(size_t)NTILES*LCAP*RSTR];
__device__ float g_frag[NFf*Hh];
__device__ float g_z[NFf*Hh];
__device__ float g_w[NFf];
__device__ float g_featsum[Hh];
__device__ float g_featsq[Hh];
__device__ float g_bn_a[Hh];
__device__ float g_bn_b[Hh];
__device__ float g_kl[1];
__device__ int   g_preserve[1];

__device__ __forceinline__ ull ffma2(ull a, ull b, ull c) {
    ull d;
    asm("fma.rn.f32x2 %0, %1, %2, %3;" : "=l"(d) : "l"(a), "l"(b), "l"(c));
    return d;
}
__device__ __forceinline__ ull packf2(float lo, float hi) {
    ull r; asm("mov.b64 %0, {%1, %2};" : "=l"(r) : "f"(lo), "f"(hi)); return r;
}
__device__ __forceinline__ void unpackf2(ull v, float& lo, float& hi) {
    asm("mov.b64 {%0, %1}, %2;" : "=f"(lo), "=f"(hi) : "l"(v));
}
__device__ __forceinline__ void red_add_v4(float* p, float a, float b, float c, float d) {
    asm volatile("red.global.add.v4.f32 [%0], {%1, %2, %3, %4};"
                 :: "l"(p), "f"(a), "f"(b), "f"(c), "f"(d) : "memory");
}

// ---------------- prologue: out0 = relu(x@W0+b0); agg0 = out0@root + cb ------
__global__ __launch_bounds__(512, 1) void k_lin0_agg(
        const float* __restrict__ x, const float* __restrict__ W0,
        const float* __restrict__ b0, const float* __restrict__ root,
        const float* __restrict__ cb, float* __restrict__ out0,
        float* __restrict__ agg) {
    extern __shared__ float sm[];
    float* sW    = sm;
    float* sroot = sm + 1936;
    float* sb    = sm + 3872;
    float* scb   = sm + 3920;
    float* srow  = sm + 3968;
    int tid = threadIdx.x;
    for (int i = tid; i < HH2; i += 512) { sW[i] = W0[i]; sroot[i] = root[i]; }
    if (tid < Hh) { sb[tid] = b0[tid]; scb[tid] = cb[tid]; }
    if (blockIdx.x == 0) {
        if (tid < Hh) { g_featsum[tid] = 0.0f; g_featsq[tid] = 0.0f; }
        if (tid == 0) { g_kl[0] = 0.0f; g_preserve[0] = 0; }
    }

    for (int base = blockIdx.x * 512; base < Nn; base += gridDim.x * 512) {
        __syncthreads();
        int lim = Nn - base; if (lim > 512) lim = 512;
        for (int i = tid; i < lim * Hh; i += 512) {
            int n = i / Hh, h = i - n * Hh;
            srow[n*45 + h] = x[(size_t)(base + n)*Hh + h];
        }
        __syncthreads();
        bool act = tid < lim;
        ull acc[22];
        float o0[Hh];
        if (act) {
            const ull* bp = (const ull*)sb;
            #pragma unroll
            for (int p = 0; p < 22; p++) acc[p] = bp[p];
            #pragma unroll 4
            for (int h = 0; h < Hh; h++) {
                float v = srow[tid*45 + h];
                ull vv = packf2(v, v);
                const ulonglong2* wr = (const ulonglong2*)&sW[h*Hh];
                #pragma unroll
                for (int q = 0; q < 11; q++) {
                    ulonglong2 w = wr[q];
                    acc[2*q]   = ffma2(vv, w.x, acc[2*q]);
                    acc[2*q+1] = ffma2(vv, w.y, acc[2*q+1]);
                }
            }
            #pragma unroll
            for (int p = 0; p < 22; p++) {
                float a, b; unpackf2(acc[p], a, b);
                o0[2*p]   = fmaxf(a, 0.0f);
                o0[2*p+1] = fmaxf(b, 0.0f);
            }
            const ull* cp = (const ull*)scb;
            #pragma unroll
            for (int p = 0; p < 22; p++) acc[p] = cp[p];
            #pragma unroll 4
            for (int h = 0; h < Hh; h++) {
                ull vv = packf2(o0[h], o0[h]);
                const ulonglong2* wr = (const ulonglong2*)&sroot[h*Hh];
                #pragma unroll
                for (int q = 0; q < 11; q++) {
                    ulonglong2 w = wr[q];
                    acc[2*q]   = ffma2(vv, w.x, acc[2*q]);
                    acc[2*q+1] = ffma2(vv, w.y, acc[2*q+1]);
                }
            }
            #pragma unroll
            for (int o = 0; o < Hh; o++) srow[tid*45 + o] = o0[o];
        }
        __syncthreads();
        for (int i = tid; i < lim * Hh; i += 512) {
            int n = i / Hh, h = i - n * Hh;
            out0[(size_t)(base + n)*Hh + h] = srow[n*45 + h];
        }
        __syncthreads();
        if (act) {
            #pragma unroll
            for (int p = 0; p < 22; p++) {
                float a, b; unpackf2(acc[p], a, b);
                srow[tid*45 + 2*p] = a; srow[tid*45 + 2*p + 1] = b;
            }
        }
        __syncthreads();
        for (int i = tid; i < lim * Hh; i += 512) {
            int n = i / Hh, h = i - n * Hh;
            agg[(size_t)(base + n)*Hh + h] = srow[n*45 + h];
        }
    }
}

// ---------------- r MLP (stride 12) + two-half Kbig ---------------------------
// half0 cols: 0..219 = d0..4 (o-major within d), 220..263 = bias
// half1 cols: 0..219 = d5..9, 220..263 = zero
__global__ void k_edge_r_kbig(const float* __restrict__ ea, const float* __restrict__ We1,
                              const float* __restrict__ be1, const float* __restrict__ We2,
                              const float* __restrict__ be2, float* __restrict__ r) {
    __shared__ float sW[EDd*EDd];
    __shared__ float sb[EDd];
    if (threadIdx.x < EDd*EDd) sW[threadIdx.x] = We1[threadIdx.x];
    if (threadIdx.x < EDd)     sb[threadIdx.x] = be1[threadIdx.x];
    __syncthreads();
    int idx = blockIdx.x * blockDim.x + threadIdx.x;
    if (idx < 2*Hh*CSTRH) {
        int half = idx / (Hh*CSTRH);
        int rem = idx - half*(Hh*CSTRH);
        int h = rem / CSTRH, c = rem - h*CSTRH;
        float v = 0.0f;
        if (c < 220) {
            int d = c / Hh + half*5, o = c % Hh;
            v = We2[d*HH2 + h*Hh + o];
        } else if (half == 0) {
            v = be2[h*Hh + (c - 220)];
        }
        g_Kbig2[idx] = v;
    }
    if (idx < Ee * EDd) {
        int e = idx / EDd, d = idx % EDd;
        const float* er = ea + e * EDd;
        float acc = sb[d];
        #pragma unroll
        for (int k = 0; k < EDd; k++) acc += er[k] * sW[k*EDd + d];
        r[e*RSTR + d] = fmaxf(acc, 0.0f);
    }
}

// ---------------- direct-indexed CSR: slot table, no scan ---------------------
__global__ void k_csr_direct(const int* __restrict__ ei) {
    int e = blockIdx.x * blockDim.x + threadIdx.x;
    if (e < Ee) {
        int s = ei[e];
        int pos = atomicAdd(&g_deg[s], 1);
        if (pos < CAP) g_tab[(size_t)s*CAP + pos] = e;
    }
}

// ---------------- per-tile scan: node offsets within tile + tile counts --------
__global__ void k_tile_scan() {
    int t = blockIdx.x;
    int n = t * TILE + threadIdx.x;
    int d = 0;
    if (n < Nn) { d = g_deg[n]; if (d > CAP) d = CAP; }
    int incl = d;
    #pragma unroll
    for (int ofs = 1; ofs < 32; ofs <<= 1) {
        int v = __shfl_up_sync(0xFFFFFFFFu, incl, ofs);
        if (threadIdx.x >= ofs) incl += v;
    }
    if (n < Nn) g_noff[n] = incl - d;
    if (threadIdx.x == 31) g_tcnt[t] = (incl < LCAP) ? incl : LCAP;
}

// ---------------- pack: per-tile contiguous (dst, ln, r) worklists -------------
__global__ void k_pack(const int* __restrict__ ei) {
    int idx = blockIdx.x * blockDim.x + threadIdx.x;
    int n = idx >> 6, p = idx & (CAP - 1);
    if (n < Nn) {
        int d = g_deg[n]; if (d > CAP) d = CAP;
        if (p < d) {
            int e = g_tab[(size_t)n*CAP + p];
            int t = n >> 5;
            int pos = g_noff[n] + p;
            if (pos < LCAP) {
                int gp = t * LCAP + pos;
                g_tdst[gp] = ei[Ee + e];
                g_tln[gp]  = n & 31;
                const float4* sr = (const float4*)&g_r[(size_t)e*RSTR];
                float4* dr = (float4*)&g_tr[(size_t)gp*RSTR];
                dr[0] = sr[0]; dr[1] = sr[1]; dr[2] = sr[2];
            }
        }
    }
}

// ---------------- fused conv, d-split halves, 2 blocks/SM ----------------------
__global__ __launch_bounds__(THC, 2) void k_fused_conv(
        const float* __restrict__ cur, float* __restrict__ agg) {
    extern __shared__ float sm[];
    float* sK   = sm;                        // 44*264 f
    float* outs = sK + Hh*CSTRH;             // 44*32 f
    float* srow = outs + Hh*TILE;            // 32*45 f
    float* ys   = srow + TILE*45;            // 32*264 f
    float* sre  = ys + TILE*CSTRH;           // 320*12 f
    int*   sln  = (int*)(sre + LCAP*RSTR);   // LCAP
    int*   sdst = sln + LCAP;                // LCAP
    int tid = threadIdx.x;
    int half = blockIdx.x & 1;

    const float* Kb = g_Kbig2 + half*(Hh*CSTRH);
    for (int i = tid; i < Hh*CSTRH; i += THC) sK[i] = Kb[i];

    for (int tile = blockIdx.x >> 1; tile < NTILES; tile += gridDim.x >> 1) {
        __syncthreads();                     // prev tile fully consumed
        int base = tile * TILE;
        int lim = Nn - base; if (lim > TILE) lim = TILE;
        int ecnt = g_tcnt[tile];
        // stage node rows + packed edge metadata (all coalesced)
        for (int i = tid; i < lim*Hh; i += THC) {
            int n = i / Hh, h = i - n*Hh;
            srow[n*45 + h] = cur[(size_t)(base + n)*Hh + h];
        }
        for (int i = tid; i < ecnt; i += THC) {
            sdst[i] = g_tdst[tile*LCAP + i];
            sln[i]  = g_tln[tile*LCAP + i];
        }
        {
            const float4* gr4 = (const float4*)&g_tr[(size_t)tile*LCAP*RSTR];
            float4* sr4 = (float4*)sre;
            for (int i = tid; i < ecnt*3; i += THC) sr4[i] = gr4[i];
        }
        __syncthreads();
        // transpose to h-major
        for (int i = tid; i < TILE*Hh; i += THC) {
            int h = i >> 5, n = i & 31;
            outs[h*TILE + n] = (n < lim) ? srow[n*45 + h] : 0.0f;
        }
        __syncthreads();

        // GEMM: 264 threads, 4-node x 4-colpair tiles; 8 lanes share B
        if (tid < 264) {
            int cg = tid >> 3, ng = tid & 7;
            int c0 = cg * 8, n0 = ng * 4;
            ull acc[4][4];
            #pragma unroll
            for (int i = 0; i < 4; i++)
                #pragma unroll
                for (int j = 0; j < 4; j++) acc[i][j] = 0ULL;
            #pragma unroll 4
            for (int h = 0; h < Hh; h++) {
                float4 a = *(const float4*)&outs[h*TILE + n0];
                ulonglong2 b0 = *(const ulonglong2*)&sK[h*CSTRH + c0];
                ulonglong2 b1 = *(const ulonglong2*)&sK[h*CSTRH + c0 + 4];
                ull av[4];
                av[0] = packf2(a.x, a.x); av[1] = packf2(a.y, a.y);
                av[2] = packf2(a.z, a.z); av[3] = packf2(a.w, a.w);
                ull bv[4] = {b0.x, b0.y, b1.x, b1.y};
                #pragma unroll
                for (int i = 0; i < 4; i++)
                    #pragma unroll
                    for (int j = 0; j < 4; j++)
                        acc[i][j] = ffma2(av[i], bv[j], acc[i][j]);
            }
            #pragma unroll
            for (int i = 0; i < 4; i++) {
                ulonglong2 s0; s0.x = acc[i][0]; s0.y = acc[i][1];
                ulonglong2 s1; s1.x = acc[i][2]; s1.y = acc[i][3];
                *(ulonglong2*)&ys[(n0 + i)*CSTRH + c0]     = s0;
                *(ulonglong2*)&ys[(n0 + i)*CSTRH + c0 + 4] = s1;
            }
        }
        __syncthreads();

        // edge phase: this half's partial message; RED accumulates across halves
        int total = ecnt * 11;
        for (int i = tid; i < total; i += THC) {
            int idx = i / 11, q = i - idx * 11;
            int ln = sln[idx], dst = sdst[idx];
            const float* rr = &sre[idx*RSTR];
            const float* yrow = &ys[ln*CSTRH];
            int qo = q * 4;
            float4 acc4;
            if (half == 0) {
                acc4 = *(const float4*)&yrow[220 + qo];
                #pragma unroll
                for (int d = 0; d < 5; d++) {
                    float rv = rr[d];
                    float4 yv = *(const float4*)&yrow[d*Hh + qo];
                    acc4.x += rv * yv.x; acc4.y += rv * yv.y;
                    acc4.z += rv * yv.z; acc4.w += rv * yv.w;
                }
            } else {
                acc4.x = acc4.y = acc4.z = acc4.w = 0.0f;
                #pragma unroll
                for (int d = 0; d < 5; d++) {
                    float rv = rr[5 + d];
                    float4 yv = *(const float4*)&yrow[d*Hh + qo];
                    acc4.x += rv * yv.x; acc4.y += rv * yv.y;
                    acc4.z += rv * yv.z; acc4.w += rv * yv.w;
                }
            }
            red_add_v4(&agg[dst*Hh + qo], acc4.x, acc4.y, acc4.z, acc4.w);
        }
    }
}

// ---------------- node update: m=relu(agg); out'=[m,out]@Wm+bm; agg'=out'@root+cb
__global__ __launch_bounds__(512, 1) void k_node_update(
        float* __restrict__ agg, const float* __restrict__ out,
        const float* __restrict__ Wm, const float* __restrict__ bm,
        const float* __restrict__ root, const float* __restrict__ cb,
        float* __restrict__ outn, int compute_agg) {
    extern __shared__ float sm[];
    float* sWm   = sm;
    float* sroot = sm + 2*HH2;
    float* sbm   = sm + 2*HH2 + HH2;
    float* scb   = sbm + 48;
    float* sagg  = scb + 48;
    float* sout  = sagg + 512*45;
    int tid = threadIdx.x;
    for (int i = tid; i < 2*HH2; i += 512) sWm[i] = Wm[i];
    for (int i = tid; i < HH2;   i += 512) sroot[i] = root[i];
    if (tid < Hh) { sbm[tid] = bm[tid]; scb[tid] = cb[tid]; }

    for (int base = blockIdx.x * 512; base < Nn; base += gridDim.x * 512) {
        __syncthreads();
        int lim = Nn - base; if (lim > 512) lim = 512;
        for (int i = tid; i < lim*Hh; i += 512) {
            int n = i / Hh, h = i - n*Hh;
            sagg[n*45 + h] = agg[(size_t)(base + n)*Hh + h];
            sout[n*45 + h] = out[(size_t)(base + n)*Hh + h];
        }
        __syncthreads();
        bool act = tid < lim;
        ull acc[22];
        float no[Hh];
        if (act) {
            const ull* bp = (const ull*)sbm;
            #pragma unroll
            for (int p = 0; p < 22; p++) acc[p] = bp[p];
            #pragma unroll 4
            for (int h = 0; h < Hh; h++) {
                float vm = fmaxf(sagg[tid*45 + h], 0.0f);
                float vo = sout[tid*45 + h];
                ull vvm = packf2(vm, vm);
                ull vvo = packf2(vo, vo);
                const ulonglong2* w1 = (const ulonglong2*)&sWm[h*Hh];
                const ulonglong2* w2 = (const ulonglong2*)&sWm[(Hh + h)*Hh];
                #pragma unroll
                for (int q = 0; q < 11; q++) {
                    ulonglong2 a = w1[q], b = w2[q];
                    acc[2*q]   = ffma2(vvm, a.x, acc[2*q]);
                    acc[2*q+1] = ffma2(vvm, a.y, acc[2*q+1]);
                    acc[2*q]   = ffma2(vvo, b.x, acc[2*q]);
                    acc[2*q+1] = ffma2(vvo, b.y, acc[2*q+1]);
                }
            }
            #pragma unroll
            for (int p = 0; p < 22; p++) unpackf2(acc[p], no[2*p], no[2*p+1]);
            #pragma unroll
            for (int o = 0; o < Hh; o++) sagg[tid*45 + o] = no[o];
            if (compute_agg) {
                const ull* cp = (const ull*)scb;
                #pragma unroll
                for (int p = 0; p < 22; p++) acc[p] = cp[p];
                #pragma unroll 4
                for (int h = 0; h < Hh; h++) {
                    ull vv = packf2(no[h], no[h]);
                    const ulonglong2* wr = (const ulonglong2*)&sroot[h*Hh];
                    #pragma unroll
                    for (int q = 0; q < 11; q++) {
                        ulonglong2 w = wr[q];
                        acc[2*q]   = ffma2(vv, w.x, acc[2*q]);
                        acc[2*q+1] = ffma2(vv, w.y, acc[2*q+1]);
                    }
                }
                #pragma unroll
                for (int p = 0; p < 22; p++) {
                    float a, b; unpackf2(acc[p], a, b);
                    sout[tid*45 + 2*p] = a; sout[tid*45 + 2*p + 1] = b;
                }
            }
        }
        __syncthreads();
        for (int i = tid; i < lim*Hh; i += 512) {
            int n = i / Hh, h = i - n*Hh;
            outn[(size_t)(base + n)*Hh + h] = sagg[n*45 + h];
        }
        if (compute_agg) {
            for (int i = tid; i < lim*Hh; i += 512) {
                int n = i / Hh, h = i - n*Hh;
                agg[(size_t)(base + n)*Hh + h] = sout[n*45 + h];
            }
        }
    }
}

// ---------------- frag build: normalize 5 nodes, mean, z, feature stats -------
__global__ __launch_bounds__(256) void k_frag_build(
        const float* __restrict__ out, const float* __restrict__ x,
        const float* __restrict__ Wc1, const float* __restrict__ bc1) {
    __shared__ float sW[HH2];
    __shared__ float sb[48];
    __shared__ float sfrag[4][48];
    __shared__ float spart[4][5][2];
    __shared__ float sfs[48], sfq[48];
    int tid = threadIdx.x;
    int ty = tid >> 6, tx = tid & 63;
    int lane = tid & 31, half = (tx >> 5);
    for (int i = tid; i < HH2; i += 256) sW[i] = Wc1[i];
    if (tid < Hh) { sb[tid] = bc1[tid]; sfs[tid] = 0.0f; sfq[tid] = 0.0f; }
    __syncthreads();

    int f = blockIdx.x * 4 + ty;
    int o = tx;
    float v[5];
    #pragma unroll
    for (int n = 0; n < 5; n++) {
        v[n] = (o < Hh) ? out[(size_t)(f*5 + n)*Hh + o] + x[(size_t)(f*5 + n)*Hh + o] : 0.0f;
        float p = v[n] * v[n];
        #pragma unroll
        for (int ofs = 16; ofs > 0; ofs >>= 1) p += __shfl_xor_sync(0xFFFFFFFFu, p, ofs);
        if (lane == 0) spart[ty][n][half] = p;
    }
    __syncthreads();
    float fv = 0.0f;
    #pragma unroll
    for (int n = 0; n < 5; n++) {
        float nrm = fmaxf(sqrtf(spart[ty][n][0] + spart[ty][n][1]), 1e-12f);
        fv += v[n] / nrm;
    }
    fv *= 0.2f;
    if (o < Hh) { sfrag[ty][o] = fv; g_frag[(size_t)f*Hh + o] = fv; }
    __syncthreads();
    if (o < Hh) {
        float acc = sb[o];
        #pragma unroll 11
        for (int h = 0; h < Hh; h++) acc += sfrag[ty][h] * sW[h*Hh + o];
        g_z[(size_t)f*Hh + o] = acc;
        atomicAdd(&sfs[o], acc);
        atomicAdd(&sfq[o], acc * acc);
    }
    __syncthreads();
    if (tid < Hh) {
        atomicAdd(&g_featsum[tid], sfs[tid]);
        atomicAdd(&g_featsq[tid], sfq[tid]);
    }
}

// ---------------- batchnorm affine fold ---------------------------------------
__global__ void k_bn(const float* __restrict__ bng, const float* __restrict__ bnb) {
    int h = threadIdx.x;
    if (h < Hh) {
        float mean = g_featsum[h] / (float)NFf;
        float var  = g_featsq[h] / (float)NFf - mean * mean;
        float a = bng[h] * rsqrtf(var + 1e-5f);
        g_bn_a[h] = a;
        g_bn_b[h] = bnb[h] - mean * a;
    }
}

// ---------------- w = sigmoid(relu(bn(z)) @ Wc2 + bc2) -------------------------
__global__ void k_frag_w(const float* __restrict__ Wc2, const float* __restrict__ bc2) {
    __shared__ float sa[Hh], sb2[Hh], sW2[Hh];
    if (threadIdx.x < Hh) {
        sa[threadIdx.x]  = g_bn_a[threadIdx.x];
        sb2[threadIdx.x] = g_bn_b[threadIdx.x];
        sW2[threadIdx.x] = Wc2[threadIdx.x];
    }
    __syncthreads();
    int f = blockIdx.x * blockDim.x + threadIdx.x;
    if (f < NFf) {
        float acc = bc2[0];
        #pragma unroll 11
        for (int h = 0; h < Hh; h++) {
            float zn = g_z[f*Hh + h] * sa[h] + sb2[h];
            acc += fmaxf(zn, 0.0f) * sW2[h];
        }
        float w = 1.0f / (1.0f + expf(-acc));
        g_w[f] = w;
        if (w > 0.5f) atomicAdd(&g_preserve[0], 1);
    }
}

// ---------------- per-graph: stats + reparam + KL + MLP head -------------------
__global__ __launch_bounds__(256) void k_graph_all(
        const float* __restrict__ noise,
        const float* __restrict__ Wp1, const float* __restrict__ bp1,
        const float* __restrict__ Wp2, const float* __restrict__ bp2,
        const float* __restrict__ Wp3, const float* __restrict__ bp3,
        float* __restrict__ out) {
    __shared__ float sfrag[10*Hh];
    __shared__ float sw[10];
    __shared__ float ssub[Hh];
    __shared__ float skl[64];
    __shared__ float h1[256];
    __shared__ float red[128];
    int g = blockIdx.x;
    int tid = threadIdx.x;
    for (int i = tid; i < 10*Hh; i += 256) sfrag[i] = g_frag[(size_t)g*10*Hh + i];
    if (tid < 10) sw[tid] = g_w[g*10 + tid];
    __syncthreads();

    float klp = 0.0f;
    if (tid < Hh) {
        int h = tid;
        float s = 0.0f, s2 = 0.0f;
        #pragma unroll
        for (int f = 0; f < 10; f++) { float v = sfrag[f*Hh + h]; s += v; s2 += v * v; }
        float mean = s * 0.1f;
        float var = (s2 - 10.0f * mean * mean) * (1.0f / 9.0f);
        float sd = sqrtf(fmaxf(var, 0.0f));
        float den = sd + 1e-7f;
        float nsub = 0.0f;
        #pragma unroll
        for (int f = 0; f < 10; f++) {
            float lp = sw[f], lnn = 1.0f - lp;
            float fv = sfrag[f*Hh + h];
            float nm = lp * fv + lnn * mean;
            float ns = lnn * sd;
            float ny = nm + noise[(size_t)(g*10 + f)*Hh + h] * ns;
            nsub += ny;
            float a = ns / den;
            float b = (nm - mean) / den;
            klp += 0.5f * a * a + b * b;
        }
        ssub[h] = nsub * 0.1f;
    }
    if (tid < 64) skl[tid] = (tid < Hh) ? klp : 0.0f;
    __syncthreads();
    for (int s = 32; s > 0; s >>= 1) {
        if (tid < s) skl[tid] += skl[tid + s];
        __syncthreads();
    }
    if (tid == 0) atomicAdd(&g_kl[0], skl[0]);

    // MLP head
    {
        float acc = bp1[tid];
        #pragma unroll 11
        for (int k = 0; k < Hh; k++) acc += ssub[k] * Wp1[k*256 + tid];
        h1[tid] = fmaxf(acc, 0.0f);
    }
    __syncthreads();
    if (tid < 128) {
        float acc = bp2[tid];
        #pragma unroll 8
        for (int k = 0; k < 256; k++) acc += h1[k] * Wp2[k*128 + tid];
        red[tid] = fmaxf(acc, 0.0f) * Wp3[tid];
    }
    __syncthreads();
    for (int s = 64; s > 0; s >>= 1) {
        if (tid < s) red[tid] += red[tid + s];
        __syncthreads();
    }
    if (tid == 0) out[g] = 1.0f / (1.0f + expf(-(red[0] + bp3[0])));
}

// ---------------- scalars -------------------------------------------------------
__global__ void k_final(float* __restrict__ out) {
    out[NGg]     = g_kl[0] / (float)(NGg * Hh);
    out[NGg + 1] = (float)g_preserve[0] / (float)NFf;
}

// ================================================================================
extern "C" void kernel_launch(void* const* d_in, const int* in_sizes, int n_in,
                              void* d_out, int out_size) {
    (void)in_sizes; (void)n_in; (void)out_size;
    const float* x       = (const float*)d_in[0];
    const float* ea      = (const float*)d_in[1];
    const float* noise   = (const float*)d_in[2];
    const float* W0      = (const float*)d_in[3];
    const float* b0      = (const float*)d_in[4];
    const float* We1     = (const float*)d_in[5];
    const float* be1     = (const float*)d_in[6];
    const float* We2     = (const float*)d_in[7];
    const float* be2     = (const float*)d_in[8];
    const float* root    = (const float*)d_in[9];
    const float* conv_b  = (const float*)d_in[10];
    const float* Wm      = (const float*)d_in[11];
    const float* bm      = (const float*)d_in[12];
    const float* Wc1     = (const float*)d_in[13];
    const float* bc1     = (const float*)d_in[14];
    const float* bn_g    = (const float*)d_in[15];
    const float* bn_b    = (const float*)d_in[16];
    const float* Wc2     = (const float*)d_in[17];
    const float* bc2     = (const float*)d_in[18];
    const float* Wp1     = (const float*)d_in[19];
    const float* bp1     = (const float*)d_in[20];
    const float* Wp2     = (const float*)d_in[21];
    const float* bp2     = (const float*)d_in[22];
    const float* Wp3     = (const float*)d_in[23];
    const float* bp3     = (const float*)d_in[24];
    const int* edge_index = (const int*)d_in[25];
    float* out = (float*)d_out;

    float *outA, *outB, *agg, *rbuf;
    int *degp;
    cudaGetSymbolAddress((void**)&outA, g_outA);
    cudaGetSymbolAddress((void**)&outB, g_outB);
    cudaGetSymbolAddress((void**)&agg,  g_agg);
    cudaGetSymbolAddress((void**)&rbuf, g_r);
    cudaGetSymbolAddress((void**)&degp, g_deg);

    const int SMEM_L0 = (2*HH2 + 96 + 512*45) * 4;                        // 108,032
    const int SMEM_FC = (Hh*CSTRH + Hh*TILE + TILE*45 + TILE*CSTRH
                         + LCAP*RSTR) * 4 + 2*LCAP*4;                     // 109,568
    const int SMEM_NU = (3*HH2 + 96 + 2*512*45) * 4;                      // 207,936
    cudaFuncSetAttribute(k_lin0_agg,   cudaFuncAttributeMaxDynamicSharedMemorySize, SMEM_L0);
    cudaFuncSetAttribute(k_fused_conv, cudaFuncAttributeMaxDynamicSharedMemorySize, SMEM_FC);
    cudaFuncSetAttribute(k_node_update,cudaFuncAttributeMaxDynamicSharedMemorySize, SMEM_NU);

    // launch 1: prologue (out0, agg0, zero small accumulators)
    k_lin0_agg<<<148, 512, SMEM_L0>>>(x, W0, b0, root, conv_b, outA, agg);
    // launch 2: edge MLP (stride-12 r) + two-half Kbig
    k_edge_r_kbig<<<(Ee*EDd + 255)/256, 256>>>(ea, We1, be1, We2, be2, rbuf);
    // memset + launches 3-5: CSR + per-tile packed worklists (built ONCE)
    cudaMemsetAsync(degp, 0, Nn * sizeof(int));
    k_csr_direct<<<(Ee + 255)/256, 256>>>(edge_index);
    k_tile_scan<<<NTILES, 32>>>();
    k_pack<<<(Nn*CAP + 255)/256, 256>>>(edge_index);

    // launches 6..11: 3 message-passing iterations (launch 6 = profiled conv)
    float* cur = outA;
    float* nxt = outB;
    for (int it = 0; it < 3; it++) {
        k_fused_conv<<<296, THC, SMEM_FC>>>(cur, agg);
        k_node_update<<<148, 512, SMEM_NU>>>(agg, cur, Wm, bm, root, conv_b,
                                             nxt, (it < 2) ? 1 : 0);
        float* t = cur; cur = nxt; nxt = t;
    }

    // post-GNN (structured segments: frag = 5 nodes, graph = 10 frags)
    k_frag_build<<<NFf/4, 256>>>(cur, x, Wc1, bc1);
    k_bn<<<1, 64>>>(bn_g, bn_b);
    k_frag_w<<<(NFf + 255)/256, 256>>>(Wc2, bc2);
    k_graph_all<<<NGg, 256>>>(noise, Wp1, bp1, Wp2, bp2, Wp3, bp3, out);
    k_final<<<1, 1>>>(out);
}

// round 9
// speedup vs baseline: 1.2692x; 1.2692x over previous
#include <cuda_runtime.h>
#include <math.h>

#define Nn 75000
#define Ee 150000
#define Hh 44
#define EDd 10
#define RSTR 12           // padded r row stride
#define NFf 15000
#define NGg 1500
#define HH2 1936
#define KSTR 492          // padded Kbig / ys row stride (floats)
#define TILE 32
#define CAP 64            // max edges recorded per src node
#define LCAP 320          // per-tile packed edge capacity
#define PF 128            // edges prefetched into smem per tile
#define NTILES ((Nn + TILE - 1) / TILE)

typedef unsigned long long ull;

// ---------------- scratch ----------------------------------------------------
__device__ float g_outA[Nn*Hh];
__device__ float g_outB[Nn*Hh];
__device__ float g_r[Ee*RSTR];
__device__ float g_Kbig[Hh*KSTR];
__device__ float g_agg[Nn*Hh];
__device__ int   g_deg[Nn];
__device__ int   g_tab[Nn*CAP];
__device__ int   g_tdst[NTILES*LCAP];
__device__ int   g_tln[NTILES*LCAP];
__device__ int   g_tcnt[NTILES];
__device__ float g_tr[(size_t)NTILES*LCAP*RSTR];
__device__ float g_frag[NFf*Hh];
__device__ float g_z[NFf*Hh];
__device__ float g_w[NFf];
__device__ float g_featsum[Hh];
__device__ float g_featsq[Hh];
__device__ float g_bn_a[Hh];
__device__ float g_bn_b[Hh];
__device__ float g_kl[1];
__device__ int   g_preserve[1];

__device__ __forceinline__ ull ffma2(ull a, ull b, ull c) {
    ull d;
    asm("fma.rn.f32x2 %0, %1, %2, %3;" : "=l"(d) : "l"(a), "l"(b), "l"(c));
    return d;
}
__device__ __forceinline__ ull packf2(float lo, float hi) {
    ull r; asm("mov.b64 %0, {%1, %2};" : "=l"(r) : "f"(lo), "f"(hi)); return r;
}
__device__ __forceinline__ void unpackf2(ull v, float& lo, float& hi) {
    asm("mov.b64 {%0, %1}, %2;" : "=f"(lo), "=f"(hi) : "l"(v));
}
__device__ __forceinline__ void red_add_v4(float* p, float a, float b, float c, float d) {
    asm volatile("red.global.add.v4.f32 [%0], {%1, %2, %3, %4};"
                 :: "l"(p), "f"(a), "f"(b), "f"(c), "f"(d) : "memory");
}

// ---------------- prologue: out0 = relu(x@W0+b0); agg0 = out0@root + cb ------
__global__ __launch_bounds__(512, 1) void k_lin0_agg(
        const float* __restrict__ x, const float* __restrict__ W0,
        const float* __restrict__ b0, const float* __restrict__ root,
        const float* __restrict__ cb, float* __restrict__ out0,
        float* __restrict__ agg) {
    extern __shared__ float sm[];
    float* sW    = sm;
    float* sroot = sm + 1936;
    float* sb    = sm + 3872;
    float* scb   = sm + 3920;
    float* srow  = sm + 3968;
    int tid = threadIdx.x;
    for (int i = tid; i < HH2; i += 512) { sW[i] = W0[i]; sroot[i] = root[i]; }
    if (tid < Hh) { sb[tid] = b0[tid]; scb[tid] = cb[tid]; }
    if (blockIdx.x == 0) {
        if (tid < Hh) { g_featsum[tid] = 0.0f; g_featsq[tid] = 0.0f; }
        if (tid == 0) { g_kl[0] = 0.0f; g_preserve[0] = 0; }
    }

    for (int base = blockIdx.x * 512; base < Nn; base += gridDim.x * 512) {
        __syncthreads();
        int lim = Nn - base; if (lim > 512) lim = 512;
        for (int i = tid; i < lim * Hh; i += 512) {
            int n = i / Hh, h = i - n * Hh;
            srow[n*45 + h] = x[(size_t)(base + n)*Hh + h];
        }
        __syncthreads();
        bool act = tid < lim;
        ull acc[22];
        float o0[Hh];
        if (act) {
            const ull* bp = (const ull*)sb;
            #pragma unroll
            for (int p = 0; p < 22; p++) acc[p] = bp[p];
            #pragma unroll 4
            for (int h = 0; h < Hh; h++) {
                float v = srow[tid*45 + h];
                ull vv = packf2(v, v);
                const ulonglong2* wr = (const ulonglong2*)&sW[h*Hh];
                #pragma unroll
                for (int q = 0; q < 11; q++) {
                    ulonglong2 w = wr[q];
                    acc[2*q]   = ffma2(vv, w.x, acc[2*q]);
                    acc[2*q+1] = ffma2(vv, w.y, acc[2*q+1]);
                }
            }
            #pragma unroll
            for (int p = 0; p < 22; p++) {
                float a, b; unpackf2(acc[p], a, b);
                o0[2*p]   = fmaxf(a, 0.0f);
                o0[2*p+1] = fmaxf(b, 0.0f);
            }
            const ull* cp = (const ull*)scb;
            #pragma unroll
            for (int p = 0; p < 22; p++) acc[p] = cp[p];
            #pragma unroll 4
            for (int h = 0; h < Hh; h++) {
                ull vv = packf2(o0[h], o0[h]);
                const ulonglong2* wr = (const ulonglong2*)&sroot[h*Hh];
                #pragma unroll
                for (int q = 0; q < 11; q++) {
                    ulonglong2 w = wr[q];
                    acc[2*q]   = ffma2(vv, w.x, acc[2*q]);
                    acc[2*q+1] = ffma2(vv, w.y, acc[2*q+1]);
                }
            }
            #pragma unroll
            for (int o = 0; o < Hh; o++) srow[tid*45 + o] = o0[o];
        }
        __syncthreads();
        for (int i = tid; i < lim * Hh; i += 512) {
            int n = i / Hh, h = i - n * Hh;
            out0[(size_t)(base + n)*Hh + h] = srow[n*45 + h];
        }
        __syncthreads();
        if (act) {
            #pragma unroll
            for (int p = 0; p < 22; p++) {
                float a, b; unpackf2(acc[p], a, b);
                srow[tid*45 + 2*p] = a; srow[tid*45 + 2*p + 1] = b;
            }
        }
        __syncthreads();
        for (int i = tid; i < lim * Hh; i += 512) {
            int n = i / Hh, h = i - n * Hh;
            agg[(size_t)(base + n)*Hh + h] = srow[n*45 + h];
        }
    }
}

// ---------------- r MLP (stride 12) + Kbig + CSR fill (merged) -----------------
__global__ void k_edge_r_kbig_csr(const float* __restrict__ ea, const float* __restrict__ We1,
                                  const float* __restrict__ be1, const float* __restrict__ We2,
                                  const float* __restrict__ be2, const int* __restrict__ ei,
                                  float* __restrict__ r) {
    __shared__ float sW[EDd*EDd];
    __shared__ float sb[EDd];
    if (threadIdx.x < EDd*EDd) sW[threadIdx.x] = We1[threadIdx.x];
    if (threadIdx.x < EDd)     sb[threadIdx.x] = be1[threadIdx.x];
    __syncthreads();
    int idx = blockIdx.x * blockDim.x + threadIdx.x;
    if (idx < Hh * KSTR) {
        int h = idx / KSTR, c = idx % KSTR;
        float v = 0.0f;
        if (c < 440)      { int d = c / Hh, o = c % Hh; v = We2[d*HH2 + h*Hh + o]; }
        else if (c < 484) { v = be2[h*Hh + (c - 440)]; }
        g_Kbig[idx] = v;
    }
    if (idx < Ee) {                      // CSR fill (g_deg zeroed by memset)
        int s = ei[idx];
        int pos = atomicAdd(&g_deg[s], 1);
        if (pos < CAP) g_tab[(size_t)s*CAP + pos] = idx;
    }
    if (idx < Ee * EDd) {
        int e = idx / EDd, d = idx % EDd;
        const float* er = ea + e * EDd;
        float acc = sb[d];
        #pragma unroll
        for (int k = 0; k < EDd; k++) acc += er[k] * sW[k*EDd + d];
        r[e*RSTR + d] = fmaxf(acc, 0.0f);
    }
}

// ---------------- merged scan + pack: per-tile contiguous worklists ------------
__global__ __launch_bounds__(256) void k_scanpack(const int* __restrict__ ei) {
    __shared__ int sdeg[TILE], soff[TILE];
    int t = blockIdx.x;
    int tid = threadIdx.x;
    if (tid < TILE) {
        int n = t * TILE + tid;
        int d = 0;
        if (n < Nn) { d = g_deg[n]; if (d > CAP) d = CAP; }
        int incl = d;
        #pragma unroll
        for (int ofs = 1; ofs < 32; ofs <<= 1) {
            int v = __shfl_up_sync(0xFFFFFFFFu, incl, ofs);
            if (tid >= ofs) incl += v;
        }
        sdeg[tid] = d;
        soff[tid] = incl - d;
        if (tid == 31) g_tcnt[t] = (incl < LCAP) ? incl : LCAP;
    }
    __syncthreads();
    for (int s = tid; s < TILE*CAP; s += 256) {
        int nl = s >> 6, p = s & (CAP - 1);
        if (p < sdeg[nl]) {
            int n = t * TILE + nl;
            int e = g_tab[(size_t)n*CAP + p];
            int pos = soff[nl] + p;
            if (pos < LCAP) {
                int gp = t * LCAP + pos;
                g_tdst[gp] = ei[Ee + e];
                g_tln[gp]  = nl;
                const float4* sr = (const float4*)&g_r[(size_t)e*RSTR];
                float4* dr = (float4*)&g_tr[(size_t)gp*RSTR];
                dr[0] = sr[0]; dr[1] = sr[1]; dr[2] = sr[2];
            }
        }
    }
}

// ---------------- fused conv: double-buffered pipelined tiles ------------------
__global__ __launch_bounds__(512, 1) void k_fused_conv(
        const float* __restrict__ cur, float* __restrict__ agg) {
    extern __shared__ float sm[];
    float* sK   = sm;                         // 44*492
    float* outs = sK + Hh*KSTR;               // 44*32
    float* srow = outs + Hh*TILE;             // 2 * 32*45
    float* ys   = srow + 2*TILE*45;           // 32*492
    float* sre  = ys + TILE*KSTR;             // 2 * PF*12
    int*   sdst = (int*)(sre + 2*PF*RSTR);    // 2*PF
    int*   sln  = sdst + 2*PF;                // 2*PF
    int tid = threadIdx.x;

    for (int i = tid; i < Hh*KSTR; i += 512) sK[i] = g_Kbig[i];

    int tile = blockIdx.x;
    int b = 0;
    int ecnt_cur = 0;
    // prologue: stage first tile into buffer 0
    {
        ecnt_cur = g_tcnt[tile];
        int base = tile * TILE;
        int lim = Nn - base; if (lim > TILE) lim = TILE;
        for (int i = tid; i < lim*Hh; i += 512) {
            int n = i / Hh, h = i - n*Hh;
            srow[n*45 + h] = cur[(size_t)base*Hh + i];
        }
        if (tid < PF*3)
            ((float4*)sre)[tid] = ((const float4*)&g_tr[(size_t)tile*LCAP*RSTR])[tid];
        if (tid < PF) {
            sdst[tid] = g_tdst[tile*LCAP + tid];
            sln[tid]  = g_tln[tile*LCAP + tid];
        }
    }
    __syncthreads();

    for (; tile < NTILES; tile += gridDim.x) {
        int base = tile * TILE;
        int lim = Nn - base; if (lim > TILE) lim = TILE;
        float* srowb = srow + b * (TILE*45);
        // transpose to h-major
        for (int i = tid; i < TILE*Hh; i += 512) {
            int h = i >> 5, n = i & 31;
            outs[h*TILE + n] = (n < lim) ? srowb[n*45 + h] : 0.0f;
        }
        __syncthreads();                          // A: outs ready

        // prefetch tile t+gridDim into registers (latency hides under GEMM)
        int ntile = tile + gridDim.x;
        bool hn = ntile < NTILES;
        int ecnt_next = 0, nlim = 0, pdst = 0, pln = 0;
        float p0 = 0.0f, p1 = 0.0f, p2 = 0.0f;
        float4 pr = make_float4(0.f, 0.f, 0.f, 0.f);
        if (hn) {
            ecnt_next = g_tcnt[ntile];
            int nbase = ntile * TILE;
            nlim = Nn - nbase; if (nlim > TILE) nlim = TILE;
            int tot = nlim * Hh;
            const float* src = cur + (size_t)nbase*Hh;
            if (tid < tot)        p0 = src[tid];
            if (tid + 512 < tot)  p1 = src[tid + 512];
            if (tid + 1024 < tot) p2 = src[tid + 1024];
            if (tid < PF*3)
                pr = ((const float4*)&g_tr[(size_t)ntile*LCAP*RSTR])[tid];
            if (tid < PF) {
                pdst = g_tdst[ntile*LCAP + tid];
                pln  = g_tln[ntile*LCAP + tid];
            }
        }

        // GEMM: 4-node x 4-colpair register tile; 8 lanes share B (broadcast)
        if (tid < 488) {
            int cg = tid >> 3, ng = tid & 7;
            int c0 = cg * 8, n0 = ng * 4;
            ull acc[4][4];
            #pragma unroll
            for (int i = 0; i < 4; i++)
                #pragma unroll
                for (int j = 0; j < 4; j++) acc[i][j] = 0ULL;
            #pragma unroll 4
            for (int h = 0; h < Hh; h++) {
                float4 a = *(const float4*)&outs[h*TILE + n0];
                ulonglong2 b0 = *(const ulonglong2*)&sK[h*KSTR + c0];
                ulonglong2 b1 = *(const ulonglong2*)&sK[h*KSTR + c0 + 4];
                ull av[4];
                av[0] = packf2(a.x, a.x); av[1] = packf2(a.y, a.y);
                av[2] = packf2(a.z, a.z); av[3] = packf2(a.w, a.w);
                ull bv[4] = {b0.x, b0.y, b1.x, b1.y};
                #pragma unroll
                for (int i = 0; i < 4; i++)
                    #pragma unroll
                    for (int j = 0; j < 4; j++)
                        acc[i][j] = ffma2(av[i], bv[j], acc[i][j]);
            }
            #pragma unroll
            for (int i = 0; i < 4; i++) {
                ulonglong2 s0; s0.x = acc[i][0]; s0.y = acc[i][1];
                ulonglong2 s1; s1.x = acc[i][2]; s1.y = acc[i][3];
                *(ulonglong2*)&ys[(n0 + i)*KSTR + c0]     = s0;
                *(ulonglong2*)&ys[(n0 + i)*KSTR + c0 + 4] = s1;
            }
        }
        __syncthreads();                          // B: ys ready

        // edge phase: (edge, quad) items; smem fast path, global fallback >= PF
        int total = ecnt_cur * 11;
        for (int i = tid; i < total; i += 512) {
            int idx = i / 11, q = i - idx * 11;
            int qo = q * 4;
            float4 a4;
            int dst;
            if (idx < PF) {
                int ln = sln[b*PF + idx]; dst = sdst[b*PF + idx];
                const float* rr = &sre[(b*PF + idx)*RSTR];
                const float* yrow = &ys[ln*KSTR];
                a4 = *(const float4*)&yrow[440 + qo];
                #pragma unroll
                for (int d = 0; d < EDd; d++) {
                    float rv = rr[d];
                    float4 yv = *(const float4*)&yrow[d*Hh + qo];
                    a4.x += rv * yv.x; a4.y += rv * yv.y;
                    a4.z += rv * yv.z; a4.w += rv * yv.w;
                }
            } else {
                int gp = tile*LCAP + idx;
                int ln = g_tln[gp]; dst = g_tdst[gp];
                const float* yrow = &ys[ln*KSTR];
                a4 = *(const float4*)&yrow[440 + qo];
                #pragma unroll
                for (int d = 0; d < EDd; d++) {
                    float rv = g_tr[(size_t)gp*RSTR + d];
                    float4 yv = *(const float4*)&yrow[d*Hh + qo];
                    a4.x += rv * yv.x; a4.y += rv * yv.y;
                    a4.z += rv * yv.z; a4.w += rv * yv.w;
                }
            }
            red_add_v4(&agg[dst*Hh + qo], a4.x, a4.y, a4.z, a4.w);
        }

        // store prefetched tile into alternate buffers
        int nb = b ^ 1;
        if (hn) {
            float* srown = srow + nb * (TILE*45);
            int tot = nlim * Hh;
            if (tid < tot)        { int n = tid/Hh,          h = tid - n*Hh;          srown[n*45 + h] = p0; }
            if (tid + 512 < tot)  { int i1 = tid + 512;  int n = i1/Hh, h = i1 - n*Hh; srown[n*45 + h] = p1; }
            if (tid + 1024 < tot) { int i2 = tid + 1024; int n = i2/Hh, h = i2 - n*Hh; srown[n*45 + h] = p2; }
            if (tid < PF*3) ((float4*)&sre[nb*PF*RSTR])[tid] = pr;
            if (tid < PF) { sdst[nb*PF + tid] = pdst; sln[nb*PF + tid] = pln; }
        }
        __syncthreads();                          // C: buffers swapped safely
        b = nb;
        ecnt_cur = ecnt_next;
    }
}

// ---------------- node update: m=relu(agg); out'=[m,out]@Wm+bm; agg'=out'@root+cb
__global__ __launch_bounds__(512, 1) void k_node_update(
        float* __restrict__ agg, const float* __restrict__ out,
        const float* __restrict__ Wm, const float* __restrict__ bm,
        const float* __restrict__ root, const float* __restrict__ cb,
        float* __restrict__ outn, int compute_agg) {
    extern __shared__ float sm[];
    float* sWm   = sm;
    float* sroot = sm + 2*HH2;
    float* sbm   = sm + 2*HH2 + HH2;
    float* scb   = sbm + 48;
    float* sagg  = scb + 48;
    float* sout  = sagg + 512*45;
    int tid = threadIdx.x;
    for (int i = tid; i < 2*HH2; i += 512) sWm[i] = Wm[i];
    for (int i = tid; i < HH2;   i += 512) sroot[i] = root[i];
    if (tid < Hh) { sbm[tid] = bm[tid]; scb[tid] = cb[tid]; }

    for (int base = blockIdx.x * 512; base < Nn; base += gridDim.x * 512) {
        __syncthreads();
        int lim = Nn - base; if (lim > 512) lim = 512;
        for (int i = tid; i < lim*Hh; i += 512) {
            int n = i / Hh, h = i - n*Hh;
            sagg[n*45 + h] = agg[(size_t)(base + n)*Hh + h];
            sout[n*45 + h] = out[(size_t)(base + n)*Hh + h];
        }
        __syncthreads();
        bool act = tid < lim;
        ull acc[22];
        float no[Hh];
        if (act) {
            const ull* bp = (const ull*)sbm;
            #pragma unroll
            for (int p = 0; p < 22; p++) acc[p] = bp[p];
            #pragma unroll 4
            for (int h = 0; h < Hh; h++) {
                float vm = fmaxf(sagg[tid*45 + h], 0.0f);
                float vo = sout[tid*45 + h];
                ull vvm = packf2(vm, vm);
                ull vvo = packf2(vo, vo);
                const ulonglong2* w1 = (const ulonglong2*)&sWm[h*Hh];
                const ulonglong2* w2 = (const ulonglong2*)&sWm[(Hh + h)*Hh];
                #pragma unroll
                for (int q = 0; q < 11; q++) {
                    ulonglong2 a = w1[q], b = w2[q];
                    acc[2*q]   = ffma2(vvm, a.x, acc[2*q]);
                    acc[2*q+1] = ffma2(vvm, a.y, acc[2*q+1]);
                    acc[2*q]   = ffma2(vvo, b.x, acc[2*q]);
                    acc[2*q+1] = ffma2(vvo, b.y, acc[2*q+1]);
                }
            }
            #pragma unroll
            for (int p = 0; p < 22; p++) unpackf2(acc[p], no[2*p], no[2*p+1]);
            #pragma unroll
            for (int o = 0; o < Hh; o++) sagg[tid*45 + o] = no[o];
            if (compute_agg) {
                const ull* cp = (const ull*)scb;
                #pragma unroll
                for (int p = 0; p < 22; p++) acc[p] = cp[p];
                #pragma unroll 4
                for (int h = 0; h < Hh; h++) {
                    ull vv = packf2(no[h], no[h]);
                    const ulonglong2* wr = (const ulonglong2*)&sroot[h*Hh];
                    #pragma unroll
                    for (int q = 0; q < 11; q++) {
                        ulonglong2 w = wr[q];
                        acc[2*q]   = ffma2(vv, w.x, acc[2*q]);
                        acc[2*q+1] = ffma2(vv, w.y, acc[2*q+1]);
                    }
                }
                #pragma unroll
                for (int p = 0; p < 22; p++) {
                    float a, b; unpackf2(acc[p], a, b);
                    sout[tid*45 + 2*p] = a; sout[tid*45 + 2*p + 1] = b;
                }
            }
        }
        __syncthreads();
        for (int i = tid; i < lim*Hh; i += 512) {
            int n = i / Hh, h = i - n*Hh;
            outn[(size_t)(base + n)*Hh + h] = sagg[n*45 + h];
        }
        if (compute_agg) {
            for (int i = tid; i < lim*Hh; i += 512) {
                int n = i / Hh, h = i - n*Hh;
                agg[(size_t)(base + n)*Hh + h] = sout[n*45 + h];
            }
        }
    }
}

// ---------------- frag build: normalize 5 nodes, mean, z, feature stats -------
__global__ __launch_bounds__(256) void k_frag_build(
        const float* __restrict__ out, const float* __restrict__ x,
        const float* __restrict__ Wc1, const float* __restrict__ bc1) {
    __shared__ float sW[HH2];
    __shared__ float sb[48];
    __shared__ float sfrag[4][48];
    __shared__ float spart[4][5][2];
    __shared__ float sfs[48], sfq[48];
    int tid = threadIdx.x;
    int ty = tid >> 6, tx = tid & 63;
    int lane = tid & 31, half = (tx >> 5);
    for (int i = tid; i < HH2; i += 256) sW[i] = Wc1[i];
    if (tid < Hh) { sb[tid] = bc1[tid]; sfs[tid] = 0.0f; sfq[tid] = 0.0f; }
    __syncthreads();

    int f = blockIdx.x * 4 + ty;
    int o = tx;
    float v[5];
    #pragma unroll
    for (int n = 0; n < 5; n++) {
        v[n] = (o < Hh) ? out[(size_t)(f*5 + n)*Hh + o] + x[(size_t)(f*5 + n)*Hh + o] : 0.0f;
        float p = v[n] * v[n];
        #pragma unroll
        for (int ofs = 16; ofs > 0; ofs >>= 1) p += __shfl_xor_sync(0xFFFFFFFFu, p, ofs);
        if (lane == 0) spart[ty][n][half] = p;
    }
    __syncthreads();
    float fv = 0.0f;
    #pragma unroll
    for (int n = 0; n < 5; n++) {
        float nrm = fmaxf(sqrtf(spart[ty][n][0] + spart[ty][n][1]), 1e-12f);
        fv += v[n] / nrm;
    }
    fv *= 0.2f;
    if (o < Hh) { sfrag[ty][o] = fv; g_frag[(size_t)f*Hh + o] = fv; }
    __syncthreads();
    if (o < Hh) {
        float acc = sb[o];
        #pragma unroll 11
        for (int h = 0; h < Hh; h++) acc += sfrag[ty][h] * sW[h*Hh + o];
        g_z[(size_t)f*Hh + o] = acc;
        atomicAdd(&sfs[o], acc);
        atomicAdd(&sfq[o], acc * acc);
    }
    __syncthreads();
    if (tid < Hh) {
        atomicAdd(&g_featsum[tid], sfs[tid]);
        atomicAdd(&g_featsq[tid], sfq[tid]);
    }
}

// ---------------- batchnorm affine fold ---------------------------------------
__global__ void k_bn(const float* __restrict__ bng, const float* __restrict__ bnb) {
    int h = threadIdx.x;
    if (h < Hh) {
        float mean = g_featsum[h] / (float)NFf;
        float var  = g_featsq[h] / (float)NFf - mean * mean;
        float a = bng[h] * rsqrtf(var + 1e-5f);
        g_bn_a[h] = a;
        g_bn_b[h] = bnb[h] - mean * a;
    }
}

// ---------------- w = sigmoid(relu(bn(z)) @ Wc2 + bc2) -------------------------
__global__ void k_frag_w(const float* __restrict__ Wc2, const float* __restrict__ bc2) {
    __shared__ float sa[Hh], sb2[Hh], sW2[Hh];
    if (threadIdx.x < Hh) {
        sa[threadIdx.x]  = g_bn_a[threadIdx.x];
        sb2[threadIdx.x] = g_bn_b[threadIdx.x];
        sW2[threadIdx.x] = Wc2[threadIdx.x];
    }
    __syncthreads();
    int f = blockIdx.x * blockDim.x + threadIdx.x;
    if (f < NFf) {
        float acc = bc2[0];
        #pragma unroll 11
        for (int h = 0; h < Hh; h++) {
            float zn = g_z[f*Hh + h] * sa[h] + sb2[h];
            acc += fmaxf(zn, 0.0f) * sW2[h];
        }
        float w = 1.0f / (1.0f + expf(-acc));
        g_w[f] = w;
        if (w > 0.5f) atomicAdd(&g_preserve[0], 1);
    }
}

// ---------------- per-graph: stats + reparam + KL + MLP head -------------------
__global__ __launch_bounds__(256) void k_graph_all(
        const float* __restrict__ noise,
        const float* __restrict__ Wp1, const float* __restrict__ bp1,
        const float* __restrict__ Wp2, const float* __restrict__ bp2,
        const float* __restrict__ Wp3, const float* __restrict__ bp3,
        float* __restrict__ out) {
    __shared__ float sfrag[10*Hh];
    __shared__ float sw[10];
    __shared__ float ssub[Hh];
    __shared__ float skl[64];
    __shared__ float h1[256];
    __shared__ float red[128];
    int g = blockIdx.x;
    int tid = threadIdx.x;
    for (int i = tid; i < 10*Hh; i += 256) sfrag[i] = g_frag[(size_t)g*10*Hh + i];
    if (tid < 10) sw[tid] = g_w[g*10 + tid];
    __syncthreads();

    float klp = 0.0f;
    if (tid < Hh) {
        int h = tid;
        float s = 0.0f, s2 = 0.0f;
        #pragma unroll
        for (int f = 0; f < 10; f++) { float v = sfrag[f*Hh + h]; s += v; s2 += v * v; }
        float mean = s * 0.1f;
        float var = (s2 - 10.0f * mean * mean) * (1.0f / 9.0f);
        float sd = sqrtf(fmaxf(var, 0.0f));
        float den = sd + 1e-7f;
        float nsub = 0.0f;
        #pragma unroll
        for (int f = 0; f < 10; f++) {
            float lp = sw[f], lnn = 1.0f - lp;
            float fv = sfrag[f*Hh + h];
            float nm = lp * fv + lnn * mean;
            float ns = lnn * sd;
            float ny = nm + noise[(size_t)(g*10 + f)*Hh + h] * ns;
            nsub += ny;
            float a = ns / den;
            float b = (nm - mean) / den;
            klp += 0.5f * a * a + b * b;
        }
        ssub[h] = nsub * 0.1f;
    }
    if (tid < 64) skl[tid] = (tid < Hh) ? klp : 0.0f;
    __syncthreads();
    for (int s = 32; s > 0; s >>= 1) {
        if (tid < s) skl[tid] += skl[tid + s];
        __syncthreads();
    }
    if (tid == 0) atomicAdd(&g_kl[0], skl[0]);

    // MLP head
    {
        float acc = bp1[tid];
        #pragma unroll 11
        for (int k = 0; k < Hh; k++) acc += ssub[k] * Wp1[k*256 + tid];
        h1[tid] = fmaxf(acc, 0.0f);
    }
    __syncthreads();
    if (tid < 128) {
        float acc = bp2[tid];
        #pragma unroll 8
        for (int k = 0; k < 256; k++) acc += h1[k] * Wp2[k*128 + tid];
        red[tid] = fmaxf(acc, 0.0f) * Wp3[tid];
    }
    __syncthreads();
    for (int s = 64; s > 0; s >>= 1) {
        if (tid < s) red[tid] += red[tid + s];
        __syncthreads();
    }
    if (tid == 0) out[g] = 1.0f / (1.0f + expf(-(red[0] + bp3[0])));
}

// ---------------- scalars -------------------------------------------------------
__global__ void k_final(float* __restrict__ out) {
    out[NGg]     = g_kl[0] / (float)(NGg * Hh);
    out[NGg + 1] = (float)g_preserve[0] / (float)NFf;
}

// ================================================================================
extern "C" void kernel_launch(void* const* d_in, const int* in_sizes, int n_in,
                              void* d_out, int out_size) {
    (void)in_sizes; (void)n_in; (void)out_size;
    const float* x       = (const float*)d_in[0];
    const float* ea      = (const float*)d_in[1];
    const float* noise   = (const float*)d_in[2];
    const float* W0      = (const float*)d_in[3];
    const float* b0      = (const float*)d_in[4];
    const float* We1     = (const float*)d_in[5];
    const float* be1     = (const float*)d_in[6];
    const float* We2     = (const float*)d_in[7];
    const float* be2     = (const float*)d_in[8];
    const float* root    = (const float*)d_in[9];
    const float* conv_b  = (const float*)d_in[10];
    const float* Wm      = (const float*)d_in[11];
    const float* bm      = (const float*)d_in[12];
    const float* Wc1     = (const float*)d_in[13];
    const float* bc1     = (const float*)d_in[14];
    const float* bn_g    = (const float*)d_in[15];
    const float* bn_b    = (const float*)d_in[16];
    const float* Wc2     = (const float*)d_in[17];
    const float* bc2     = (const float*)d_in[18];
    const float* Wp1     = (const float*)d_in[19];
    const float* bp1     = (const float*)d_in[20];
    const float* Wp2     = (const float*)d_in[21];
    const float* bp2     = (const float*)d_in[22];
    const float* Wp3     = (const float*)d_in[23];
    const float* bp3     = (const float*)d_in[24];
    const int* edge_index = (const int*)d_in[25];
    float* out = (float*)d_out;

    float *outA, *outB, *agg, *rbuf;
    int *degp;
    cudaGetSymbolAddress((void**)&outA, g_outA);
    cudaGetSymbolAddress((void**)&outB, g_outB);
    cudaGetSymbolAddress((void**)&agg,  g_agg);
    cudaGetSymbolAddress((void**)&rbuf, g_r);
    cudaGetSymbolAddress((void**)&degp, g_deg);

    const int SMEM_L0 = (2*HH2 + 96 + 512*45) * 4;                        // 108,032
    const int SMEM_FC = (Hh*KSTR + Hh*TILE + 2*TILE*45 + TILE*KSTR
                         + 2*PF*RSTR) * 4 + 4*PF*4;                       // ~181 KB
    const int SMEM_NU = (3*HH2 + 96 + 2*512*45) * 4;                      // 207,936
    cudaFuncSetAttribute(k_lin0_agg,   cudaFuncAttributeMaxDynamicSharedMemorySize, SMEM_L0);
    cudaFuncSetAttribute(k_fused_conv, cudaFuncAttributeMaxDynamicSharedMemorySize, SMEM_FC);
    cudaFuncSetAttribute(k_node_update,cudaFuncAttributeMaxDynamicSharedMemorySize, SMEM_NU);

    // memset before any launches so launch #2's CSR fill sees zeroed degrees
    cudaMemsetAsync(degp, 0, Nn * sizeof(int));
    // launch 1: prologue (out0, agg0, zero small accumulators)
    k_lin0_agg<<<148, 512, SMEM_L0>>>(x, W0, b0, root, conv_b, outA, agg);
    // launch 2: edge MLP + Kbig + CSR fill (merged)
    k_edge_r_kbig_csr<<<(Ee*EDd + 255)/256, 256>>>(ea, We1, be1, We2, be2,
                                                   edge_index, rbuf);
    // launch 3: merged scan + pack (per-tile contiguous worklists, built ONCE)
    k_scanpack<<<NTILES, 256>>>(edge_index);

    // launches 4..9: 3 message-passing iterations (launch 4 = profiled conv)
    float* cur = outA;
    float* nxt = outB;
    for (int it = 0; it < 3; it++) {
        k_fused_conv<<<148, 512, SMEM_FC>>>(cur, agg);
        k_node_update<<<148, 512, SMEM_NU>>>(agg, cur, Wm, bm, root, conv_b,
                                             nxt, (it < 2) ? 1 : 0);
        float* t = cur; cur = nxt; nxt = t;
    }

    // post-GNN (structured segments: frag = 5 nodes, graph = 10 frags)
    k_frag_build<<<NFf/4, 256>>>(cur, x, Wc1, bc1);
    k_bn<<<1, 64>>>(bn_g, bn_b);
    k_frag_w<<<(NFf + 255)/256, 256>>>(Wc2, bc2);
    k_graph_all<<<NGg, 256>>>(noise, Wp1, bp1, Wp2, bp2, Wp3, bp3, out);
    k_final<<<1, 1>>>(out);
}